// round 2
// baseline (speedup 1.0000x reference)
#include <cuda_runtime.h>

// FiniteDifference: x [B=4, T=16, H=128, W=128, C=16] fp32
// out = concat(dy (d/dH), dx (d/dW), dz (d/dT)).
// Central difference, zero padding: out[i] = x[i+1] - x[i-1].
//
// R2: 2 float4 per thread (same pixel -> shared predicates), 12 front-batched
// LDG.128 for MLP, __stcs streaming stores so the 192 MiB output stream
// doesn't evict the 64 MiB input from L2 (T-neighbors are +-1 MiB away).

#define N4_TOTAL (4 * 16 * 128 * 128 * 4)  // 4,194,304 float4 elements

__device__ __forceinline__ float4 sub4(float4 a, float4 b) {
    return make_float4(a.x - b.x, a.y - b.y, a.z - b.z, a.w - b.w);
}

__global__ void __launch_bounds__(256)
fd_kernel(const float4* __restrict__ x, float4* __restrict__ out)
{
    int tid = blockIdx.x * blockDim.x + threadIdx.x;
    int i = tid * 2;  // two consecutive float4 within the same pixel (c4 pair)

    int w = (i >> 2)  & 127;
    int h = (i >> 9)  & 127;
    int t = (i >> 16) & 15;

    const float4 zero = make_float4(0.f, 0.f, 0.f, 0.f);

    // Front-batched loads: 12 independent LDG.128
    float4 hp0 = (h < 127) ? __ldg(&x[i + 512])     : zero;
    float4 hp1 = (h < 127) ? __ldg(&x[i + 513])     : zero;
    float4 hm0 = (h > 0)   ? __ldg(&x[i - 512])     : zero;
    float4 hm1 = (h > 0)   ? __ldg(&x[i - 511])     : zero;
    float4 wp0 = (w < 127) ? __ldg(&x[i + 4])       : zero;
    float4 wp1 = (w < 127) ? __ldg(&x[i + 5])       : zero;
    float4 wm0 = (w > 0)   ? __ldg(&x[i - 4])       : zero;
    float4 wm1 = (w > 0)   ? __ldg(&x[i - 3])       : zero;
    float4 tp0 = (t < 15)  ? __ldg(&x[i + 65536])   : zero;
    float4 tp1 = (t < 15)  ? __ldg(&x[i + 65537])   : zero;
    float4 tm0 = (t > 0)   ? __ldg(&x[i - 65536])   : zero;
    float4 tm1 = (t > 0)   ? __ldg(&x[i - 65535])   : zero;

    // Streaming stores (evict-first): keep input resident in L2
    __stcs(&out[i],                    sub4(hp0, hm0));
    __stcs(&out[i + 1],                sub4(hp1, hm1));
    __stcs(&out[i + N4_TOTAL],         sub4(wp0, wm0));
    __stcs(&out[i + N4_TOTAL + 1],     sub4(wp1, wm1));
    __stcs(&out[i + 2 * N4_TOTAL],     sub4(tp0, tm0));
    __stcs(&out[i + 2 * N4_TOTAL + 1], sub4(tp1, tm1));
}

extern "C" void kernel_launch(void* const* d_in, const int* in_sizes, int n_in,
                              void* d_out, int out_size)
{
    const float4* x = (const float4*)d_in[0];
    float4* out = (float4*)d_out;

    const int threads = 256;
    const int blocks = (N4_TOTAL / 2) / threads;  // 8192
    fd_kernel<<<blocks, threads>>>(x, out);
}

// round 3
// speedup vs baseline: 1.3211x; 1.3211x over previous
#include <cuda_runtime.h>

// FiniteDifference: x [B=4, T=16, H=128, W=128, C=16] fp32
// out = concat(dy (d/dH), dx (d/dW), dz (d/dT)).
// Central difference, zero padding: out[i] = x[i+1] - x[i-1].
//
// R3: R1 structure (1 float4/thread, low regs, high occupancy) + __stcs
// streaming stores ONLY. Output is 192 MiB write-once; evict-first stores
// keep the 64 MiB input resident in L2 so +-T re-reads (+-1 MiB away) hit L2.

#define N4_TOTAL (4 * 16 * 128 * 128 * 4)  // 4,194,304 float4 elements

__device__ __forceinline__ float4 sub4(float4 a, float4 b) {
    return make_float4(a.x - b.x, a.y - b.y, a.z - b.z, a.w - b.w);
}

__global__ void __launch_bounds__(256)
fd_kernel(const float4* __restrict__ x, float4* __restrict__ out)
{
    int i = blockIdx.x * blockDim.x + threadIdx.x;

    int w = (i >> 2)  & 127;
    int h = (i >> 9)  & 127;
    int t = (i >> 16) & 15;

    const float4 zero = make_float4(0.f, 0.f, 0.f, 0.f);

    float4 hp = (h < 127) ? x[i + 512]   : zero;
    float4 hm = (h > 0)   ? x[i - 512]   : zero;
    float4 wp = (w < 127) ? x[i + 4]     : zero;
    float4 wm = (w > 0)   ? x[i - 4]     : zero;
    float4 tp = (t < 15)  ? x[i + 65536] : zero;
    float4 tm = (t > 0)   ? x[i - 65536] : zero;

    __stcs(&out[i],                sub4(hp, hm));
    __stcs(&out[i + N4_TOTAL],     sub4(wp, wm));
    __stcs(&out[i + 2 * N4_TOTAL], sub4(tp, tm));
}

extern "C" void kernel_launch(void* const* d_in, const int* in_sizes, int n_in,
                              void* d_out, int out_size)
{
    const float4* x = (const float4*)d_in[0];
    float4* out = (float4*)d_out;

    const int threads = 256;
    const int blocks = N4_TOTAL / threads;  // 16384
    fd_kernel<<<blocks, threads>>>(x, out);
}